// round 16
// baseline (speedup 1.0000x reference)
#include <cuda_runtime.h>
#include <cuda_fp16.h>
#include <cstdint>
#include <math.h>

// ---------------------------------------------------------------------------
// Problem constants
// ---------------------------------------------------------------------------
#define NVOX   131072
#define CIN    256
#define NH     16
#define DK     32
#define DV     16
#define VD     256
#define CAT    1536
#define QKV    1280
#define FF     1024
#define MTILES (NVOX / 128)     // 1024

// ---------------------------------------------------------------------------
// Device scratch
// ---------------------------------------------------------------------------
__device__ __half g_WcatT[CAT * CIN];        // [1536,256] K-major fp16
__device__ __half g_W1T[FF * VD];            // [1024,256]
__device__ __half g_WoT[VD * FF];            // [256,1024]
__device__ float  g_bcat[CAT];
__device__ float  g_bnscale[VD];
__device__ float  g_bnbias[VD];
__device__ __half g_xh[(size_t)NVOX * CIN];
__device__ __half g_qkvh[(size_t)NVOX * QKV];
__device__ float  g_res[(size_t)NVOX * VD];  // residual branch f32
__device__ __half g_attnh[(size_t)NVOX * VD];
__device__ __half g_interh[(size_t)NVOX * FF];

// ---------------------------------------------------------------------------
// PTX helpers
// ---------------------------------------------------------------------------
__device__ __forceinline__ uint32_t smem_u32(const void* p) {
    uint32_t a;
    asm("{ .reg .u64 t; cvta.to.shared.u64 t, %1; cvt.u32.u64 %0, t; }"
        : "=r"(a) : "l"(p));
    return a;
}
__device__ __forceinline__ void cp16(uint32_t dst, const void* src) {
    asm volatile("cp.async.cg.shared.global [%0], [%1], 16;"
                 :: "r"(dst), "l"(src) : "memory");
}
__device__ __forceinline__ void cp_commit() {
    asm volatile("cp.async.commit_group;" ::: "memory");
}
template<int N>
__device__ __forceinline__ void cp_wait() {
    asm volatile("cp.async.wait_group %0;" :: "n"(N) : "memory");
}
__device__ __forceinline__ uint32_t lds32(uint32_t a) {
    uint32_t v; asm volatile("ld.shared.b32 %0, [%1];" : "=r"(v) : "r"(a)); return v;
}
__device__ __forceinline__ uint32_t lds16(uint32_t a) {
    uint32_t v; asm volatile("ld.shared.u16 %0, [%1];" : "=r"(v) : "r"(a)); return v;
}
#define LDSM4(R, addr) \
    asm volatile("ldmatrix.sync.aligned.m8n8.x4.shared.b16 {%0,%1,%2,%3}, [%4];" \
                 : "=r"((R)[0]), "=r"((R)[1]), "=r"((R)[2]), "=r"((R)[3]) \
                 : "r"(addr))

__device__ __forceinline__ void mma16816(float* d, const uint32_t* a,
                                         uint32_t b0, uint32_t b1) {
    asm volatile(
        "mma.sync.aligned.m16n8k16.row.col.f32.f16.f16.f32 "
        "{%0,%1,%2,%3}, {%4,%5,%6,%7}, {%8,%9}, {%0,%1,%2,%3};"
        : "+f"(d[0]), "+f"(d[1]), "+f"(d[2]), "+f"(d[3])
        : "r"(a[0]), "r"(a[1]), "r"(a[2]), "r"(a[3]), "r"(b0), "r"(b1));
}

// 128B rows, 8 chunks of 16B, conflict-free for ldmatrix & cp.async
__device__ __forceinline__ int swz128(int r, int c) {
    return (r << 7) | (((c ^ r) & 7) << 4);
}
// 512B rows, 32 chunks of 16B; XOR within each 8-chunk (128B) group
__device__ __forceinline__ int swzB512(int r, int c) {
    return (r << 9) | (((c & 24) | ((c ^ r) & 7)) << 4);
}

// ---------------------------------------------------------------------------
// Fused prep: blocks [0,512) pack weights/biases/BN; blocks [512,4608) x->fp16.
// ---------------------------------------------------------------------------
__global__ void prep_kernel(const float4* __restrict__ x4, uint2* __restrict__ xh,
                            const float* __restrict__ Wq, const float* __restrict__ bq,
                            const float* __restrict__ Wk, const float* __restrict__ bk,
                            const float* __restrict__ Wv, const float* __restrict__ bv,
                            const float* __restrict__ W1,
                            const float* __restrict__ Wo,
                            const float* __restrict__ Wc, const float* __restrict__ bc,
                            const float* __restrict__ gamma, const float* __restrict__ beta,
                            const float* __restrict__ mu, const float* __restrict__ var)
{
    if (blockIdx.x < 512) {
        int idx = blockIdx.x * blockDim.x + threadIdx.x;
        const int st = 512 * 256;
        for (int i = idx; i < CAT * CIN; i += st) {
            int n = i >> 8, k = i & 255;
            float w;
            if (n < 512)       w = Wq[k * 512 + n];
            else if (n < 1024) w = Wk[k * 512 + (n - 512)];
            else if (n < 1280) w = Wv[k * 256 + (n - 1024)];
            else               w = Wc[k * 256 + (n - 1280)];
            g_WcatT[i] = __float2half_rn(w);
        }
        for (int i = idx; i < FF * VD; i += st) {
            int n = i >> 8, k = i & 255;
            g_W1T[i] = __float2half_rn(W1[k * FF + n]);
        }
        for (int i = idx; i < VD * FF; i += st) {
            int n = i >> 10, k = i & 1023;
            g_WoT[i] = __float2half_rn(Wo[k * VD + n]);
        }
        for (int i = idx; i < CAT; i += st) {
            float b;
            if (i < 512)       b = bq[i];
            else if (i < 1024) b = bk[i - 512];
            else if (i < 1280) b = bv[i - 1024];
            else               b = bc[i - 1280];
            g_bcat[i] = b;
        }
        for (int i = idx; i < VD; i += st) {
            float s = gamma[i] * rsqrtf(var[i] + 1e-6f);
            g_bnscale[i] = s;
            g_bnbias[i]  = beta[i] - mu[i] * s;
        }
    } else {
        const int n4 = NVOX * CIN / 4;
        int idx = (blockIdx.x - 512) * blockDim.x + threadIdx.x;
        const int st = 4096 * 256;
        for (int i = idx; i < n4; i += st) {
            float4 v = x4[i];
            __half2 h0 = __floats2half2_rn(v.x, v.y);
            __half2 h1 = __floats2half2_rn(v.z, v.w);
            uint2 w;
            w.x = *reinterpret_cast<uint32_t*>(&h0);
            w.y = *reinterpret_cast<uint32_t*>(&h1);
            xh[i] = w;
        }
    }
}

// ---------------------------------------------------------------------------
// PERSISTENT B-resident GEMM (K=256): CTA owns one 128-col group, loads the
// 64 KB B tile once, then loops over M-tiles (stride YC) as one continuous
// 3-stage A pipeline. 256 thr, 8 warps (2x4), 64x32 warp tiles, 2 CTAs/SM.
//   MODE 0: cols<1280 -> fp16 qkv (stride 1280); cols>=1280 -> relu f32 res
//   MODE 1: relu -> fp16
// ---------------------------------------------------------------------------
template<int MODE, int YC>
__global__ __launch_bounds__(256, 2)
void gemm_bres(const __half* __restrict__ A, const __half* __restrict__ BT,
               void* __restrict__ Cv, float* __restrict__ resf,
               int Nn, const float* __restrict__ bias)
{
    extern __shared__ char sm[];
    const uint32_t bU = smem_u32(sm);            // B: 64 KB
    const uint32_t aU = bU + 65536;              // A stages: 3 x 16 KB

    const int tid  = threadIdx.x;
    const int wid  = tid >> 5;
    const int lane = tid & 31;
    const int wr = wid >> 2;
    const int wc = wid & 3;
    const int group = lane >> 2;
    const int tig = lane & 3;

    const int col0 = blockIdx.x * 128;
    const int mt0  = blockIdx.y;                 // first M-tile; stride YC
    const int nMT  = (MTILES - mt0 + YC - 1) / YC;
    const int NT   = nMT * 4;                    // total k-steps

    float acc[4][4][4];
    #pragma unroll
    for (int mi = 0; mi < 4; mi++)
        #pragma unroll
        for (int ni = 0; ni < 4; ni++)
            #pragma unroll
            for (int r = 0; r < 4; r++) acc[mi][ni][r] = 0.0f;

    // ---- B resident load (once): 128 rows x 32 chunks = 16 cp16/thread ----
    {
        #pragma unroll
        for (int i = 0; i < 16; i++) {
            int idx = tid + 256 * i;
            int r = idx >> 5, c = idx & 31;
            cp16(bU + swzB512(r, c), &BT[(size_t)(col0 + r) * CIN + c * 8]);
        }
        cp_commit();
    }

    const int ldr = tid >> 3;
    const int ldc = tid & 7;
    auto rowbase = [&](int t) -> int {           // row0 of the M-tile of step t
        return (mt0 + (t >> 2) * YC) << 7;
    };
    auto ldgstsA = [&](int t) {
        const uint32_t aS = aU + (t % 3) * 16384;
        const int row0 = rowbase(t);
        const int k0 = (t & 3) * 64;
        #pragma unroll
        for (int i = 0; i < 4; i++) {
            int r = ldr + 32 * i;
            cp16(aS + swz128(r, ldc), &A[(size_t)(row0 + r) * CIN + k0 + ldc * 8]);
        }
        cp_commit();
    };

    const int ar = lane & 15, ahi = lane >> 4;
    const int br = (lane & 7) + (lane >> 4) * 8, bhi = (lane >> 3) & 1;

    auto compute = [&](int t) {
        const uint32_t aS = aU + (t % 3) * 16384;
        const int cb = (t & 3) * 8;
        #pragma unroll
        for (int ks = 0; ks < 4; ks++) {
            uint32_t af[4][4], bf[2][4];
            #pragma unroll
            for (int mi = 0; mi < 4; mi++)
                LDSM4(af[mi], aS + swz128(wr * 64 + mi * 16 + ar, ks * 2 + ahi));
            #pragma unroll
            for (int nip = 0; nip < 2; nip++)
                LDSM4(bf[nip], bU + swzB512(wc * 32 + nip * 16 + br,
                                            cb + ks * 2 + bhi));
            #pragma unroll
            for (int mi = 0; mi < 4; mi++)
                #pragma unroll
                for (int ni = 0; ni < 4; ni++) {
                    const int nip = ni >> 1, h = ni & 1;
                    mma16816(acc[mi][ni], af[mi], bf[nip][h * 2], bf[nip][h * 2 + 1]);
                }
        }
    };

    auto epilogue = [&](int row0) {
        __half* Ch = (__half*)Cv;
        #pragma unroll
        for (int mi = 0; mi < 4; mi++) {
            #pragma unroll
            for (int ni = 0; ni < 4; ni++) {
                const int cg = col0 + wc * 32 + ni * 8 + tig * 2;
                const float bi0 = __ldg(&bias[cg]);
                const float bi1 = __ldg(&bias[cg + 1]);
                #pragma unroll
                for (int hf = 0; hf < 2; hf++) {
                    const size_t r = (size_t)row0 + wr * 64 + mi * 16 + group + hf * 8;
                    float v0 = acc[mi][ni][hf * 2 + 0] + bi0;
                    float v1 = acc[mi][ni][hf * 2 + 1] + bi1;
                    if (MODE == 0) {
                        if (cg < QKV) {
                            __half2 h = __floats2half2_rn(v0, v1);
                            *reinterpret_cast<uint32_t*>(&Ch[r * QKV + cg]) =
                                *reinterpret_cast<uint32_t*>(&h);
                        } else {
                            float2 f = make_float2(fmaxf(v0, 0.0f), fmaxf(v1, 0.0f));
                            *reinterpret_cast<float2*>(&resf[r * VD + (cg - QKV)]) = f;
                        }
                    } else {
                        __half2 h = __floats2half2_rn(fmaxf(v0, 0.0f), fmaxf(v1, 0.0f));
                        *reinterpret_cast<uint32_t*>(&Ch[r * Nn + cg]) =
                            *reinterpret_cast<uint32_t*>(&h);
                    }
                    acc[mi][ni][hf * 2 + 0] = 0.0f;
                    acc[mi][ni][hf * 2 + 1] = 0.0f;
                }
            }
        }
    };

    // prologue groups in flight: {B, A(0), A(1)}
    ldgstsA(0);
    if (NT > 1) ldgstsA(1);

    for (int t = 0; t < NT; t++) {
        if (t + 1 < NT) cp_wait<1>(); else cp_wait<0>();
        __syncthreads();
        if (t + 2 < NT) ldgstsA(t + 2);
        compute(t);
        if ((t & 3) == 3) epilogue(rowbase(t));
    }
}

// ---------------------------------------------------------------------------
// Streaming GEMM (K=1024 final GEMM): out = (res + acc + bias)*bns + bnb
// ---------------------------------------------------------------------------
#define BKT 64
#define STAGE_BYTES 32768
#define NSTAGE 3

__global__ __launch_bounds__(256, 2)
void gemm_out(const __half* __restrict__ A, const __half* __restrict__ BT,
              float* __restrict__ Cf, const float* __restrict__ resf,
              const float* __restrict__ bias)
{
    extern __shared__ char sm[];
    const uint32_t smemU = smem_u32(sm);

    const int tid  = threadIdx.x;
    const int wid  = tid >> 5;
    const int lane = tid & 31;
    const int wr = wid >> 2;
    const int wc = wid & 3;
    const int group = lane >> 2;
    const int tig = lane & 3;

    const int row0 = blockIdx.y * 128;
    const int col0 = blockIdx.x * 128;
    const int K = FF;
    const int KT = K / BKT;   // 16

    float acc[4][4][4];
    #pragma unroll
    for (int mi = 0; mi < 4; mi++)
        #pragma unroll
        for (int ni = 0; ni < 4; ni++)
            #pragma unroll
            for (int r = 0; r < 4; r++) acc[mi][ni][r] = 0.0f;

    const int ldr = tid >> 3;
    const int ldc = tid & 7;

    auto ldgsts = [&](int stage, int k0) {
        const uint32_t aS = smemU + stage * STAGE_BYTES;
        const uint32_t bS = aS + 16384;
        #pragma unroll
        for (int i = 0; i < 4; i++) {
            int r = ldr + 32 * i;
            cp16(aS + swz128(r, ldc), &A[(size_t)(row0 + r) * K + k0 + ldc * 8]);
            cp16(bS + swz128(r, ldc), &BT[(size_t)(col0 + r) * K + k0 + ldc * 8]);
        }
        cp_commit();
    };

    const int ar = lane & 15, ahi = lane >> 4;
    const int br = (lane & 7) + (lane >> 4) * 8, bhi = (lane >> 3) & 1;

    auto compute = [&](int stage) {
        const uint32_t aS = smemU + stage * STAGE_BYTES;
        const uint32_t bS = aS + 16384;
        #pragma unroll
        for (int ks = 0; ks < 4; ks++) {
            uint32_t af[4][4], bf[2][4];
            #pragma unroll
            for (int mi = 0; mi < 4; mi++)
                LDSM4(af[mi], aS + swz128(wr * 64 + mi * 16 + ar, ks * 2 + ahi));
            #pragma unroll
            for (int nip = 0; nip < 2; nip++)
                LDSM4(bf[nip], bS + swz128(wc * 32 + nip * 16 + br, ks * 2 + bhi));
            #pragma unroll
            for (int mi = 0; mi < 4; mi++)
                #pragma unroll
                for (int ni = 0; ni < 4; ni++) {
                    const int nip = ni >> 1, h = ni & 1;
                    mma16816(acc[mi][ni], af[mi], bf[nip][h * 2], bf[nip][h * 2 + 1]);
                }
        }
    };

    ldgsts(0, 0);
    ldgsts(1, BKT);
    for (int kt = 0; kt < KT; kt++) {
        if (kt + 1 < KT) cp_wait<1>(); else cp_wait<0>();
        __syncthreads();
        if (kt + 2 < KT) ldgsts((kt + 2) % NSTAGE, (kt + 2) * BKT);
        compute(kt % NSTAGE);
    }

    #pragma unroll
    for (int mi = 0; mi < 4; mi++) {
        #pragma unroll
        for (int ni = 0; ni < 4; ni++) {
            const int cg = col0 + wc * 32 + ni * 8 + tig * 2;
            const float bi0 = __ldg(&bias[cg]);
            const float bi1 = __ldg(&bias[cg + 1]);
            const float s0 = g_bnscale[cg], s1 = g_bnscale[cg + 1];
            const float d0 = g_bnbias[cg],  d1 = g_bnbias[cg + 1];
            #pragma unroll
            for (int hf = 0; hf < 2; hf++) {
                const size_t r = (size_t)row0 + wr * 64 + mi * 16 + group + hf * 8;
                float2 rr = *reinterpret_cast<const float2*>(&resf[r * VD + cg]);
                float2 f;
                f.x = (rr.x + acc[mi][ni][hf * 2 + 0] + bi0) * s0 + d0;
                f.y = (rr.y + acc[mi][ni][hf * 2 + 1] + bi1) * s1 + d1;
                *reinterpret_cast<float2*>(&Cf[r * VD + cg]) = f;
            }
        }
    }
}

// ---------------------------------------------------------------------------
// Tensor-core attention: one warp per voxel (unchanged — at DRAM floor)
// ---------------------------------------------------------------------------
#define VOX_B   3328
#define SCALE_S 0.17677669529663687f

__global__ __launch_bounds__(256)
void attn_mma_kernel(const __half* __restrict__ qkvh, __half* __restrict__ outh)
{
    __shared__ __align__(16) char sm[8 * VOX_B];
    const uint32_t smemU = smem_u32(sm);

    const int tid  = threadIdx.x;
    const int wid  = tid >> 5;
    const int lane = tid & 31;
    const size_t vox0 = (size_t)blockIdx.x * 8;

    for (int i = tid; i < 1280; i += 256) {
        int slot = i / 160;
        int j = i - slot * 160;
        int off;
        if (j < 64)       off = (j >> 2) * 80 + (j & 3) * 16;
        else if (j < 128) off = 1280 + ((j - 64) >> 2) * 80 + ((j - 64) & 3) * 16;
        else              off = 2560 + ((j - 128) >> 1) * 48 + ((j - 128) & 1) * 16;
        cp16(smemU + slot * VOX_B + off, qkvh + (vox0 + slot) * QKV + j * 8);
    }
    cp_commit();
    cp_wait<0>();
    __syncthreads();

    const uint32_t qb = smemU + wid * VOX_B;
    const uint32_t kb = qb + 1280;
    const uint32_t vb = qb + 2560;
    const int g4 = lane >> 2;
    const int t4 = lane & 3;

    float sacc[2][4];
    #pragma unroll
    for (int nt = 0; nt < 2; nt++)
        #pragma unroll
        for (int r = 0; r < 4; r++) sacc[nt][r] = 0.0f;

    #pragma unroll
    for (int ks = 0; ks < 2; ks++) {
        uint32_t a[4];
        a[0] = lds32(qb + g4 * 80       + ks * 32 + t4 * 4);
        a[1] = lds32(qb + (g4 + 8) * 80 + ks * 32 + t4 * 4);
        a[2] = lds32(qb + g4 * 80       + ks * 32 + t4 * 4 + 16);
        a[3] = lds32(qb + (g4 + 8) * 80 + ks * 32 + t4 * 4 + 16);
        #pragma unroll
        for (int nt = 0; nt < 2; nt++) {
            uint32_t b0 = lds32(kb + (nt * 8 + g4) * 80 + ks * 32 + t4 * 4);
            uint32_t b1 = lds32(kb + (nt * 8 + g4) * 80 + ks * 32 + t4 * 4 + 16);
            mma16816(sacc[nt], a, b0, b1);
        }
    }

    uint32_t af[4];
    #pragma unroll
    for (int hf = 0; hf < 2; hf++) {
        float v00 = sacc[0][hf * 2]     * SCALE_S;
        float v01 = sacc[0][hf * 2 + 1] * SCALE_S;
        float v10 = sacc[1][hf * 2]     * SCALE_S;
        float v11 = sacc[1][hf * 2 + 1] * SCALE_S;
        float mx = fmaxf(fmaxf(v00, v01), fmaxf(v10, v11));
        mx = fmaxf(mx, __shfl_xor_sync(0xffffffffu, mx, 1));
        mx = fmaxf(mx, __shfl_xor_sync(0xffffffffu, mx, 2));
        float e00 = __expf(v00 - mx), e01 = __expf(v01 - mx);
        float e10 = __expf(v10 - mx), e11 = __expf(v11 - mx);
        float sum = e00 + e01 + e10 + e11;
        sum += __shfl_xor_sync(0xffffffffu, sum, 1);
        sum += __shfl_xor_sync(0xffffffffu, sum, 2);
        float inv = 1.0f / sum;
        __half2 p0 = __floats2half2_rn(e00 * inv, e01 * inv);
        __half2 p1 = __floats2half2_rn(e10 * inv, e11 * inv);
        af[hf]     = *reinterpret_cast<uint32_t*>(&p0);
        af[hf + 2] = *reinterpret_cast<uint32_t*>(&p1);
    }

    float oacc[2][4];
    #pragma unroll
    for (int nt = 0; nt < 2; nt++)
        #pragma unroll
        for (int r = 0; r < 4; r++) oacc[nt][r] = 0.0f;

    #pragma unroll
    for (int nt = 0; nt < 2; nt++) {
        uint32_t b[2];
        #pragma unroll
        for (int reg = 0; reg < 2; reg++) {
            int jr = 2 * t4 + reg * 8;
            uint32_t lo = lds16(vb + jr * 48       + (nt * 8 + g4) * 2);
            uint32_t hi = lds16(vb + (jr + 1) * 48 + (nt * 8 + g4) * 2);
            b[reg] = lo | (hi << 16);
        }
        mma16816(oacc[nt], af, b[0], b[1]);
    }

    __half* dst = outh + (vox0 + wid) * VD;
    #pragma unroll
    for (int nt = 0; nt < 2; nt++) {
        #pragma unroll
        for (int hf = 0; hf < 2; hf++) {
            __half2 h = __floats2half2_rn(oacc[nt][hf * 2], oacc[nt][hf * 2 + 1]);
            int r = g4 + 8 * hf;
            int c = nt * 8 + 2 * t4;
            *reinterpret_cast<uint32_t*>(&dst[r * DV + c]) =
                *reinterpret_cast<uint32_t*>(&h);
        }
    }
}

// ---------------------------------------------------------------------------
// Launch
// ---------------------------------------------------------------------------
extern "C" void kernel_launch(void* const* d_in, const int* in_sizes, int n_in,
                              void* d_out, int out_size)
{
    const float* x     = (const float*)d_in[0];
    const float* Wq    = (const float*)d_in[1];
    const float* bq    = (const float*)d_in[2];
    const float* Wk    = (const float*)d_in[3];
    const float* bk    = (const float*)d_in[4];
    const float* Wv    = (const float*)d_in[5];
    const float* bv    = (const float*)d_in[6];
    const float* W1    = (const float*)d_in[7];
    const float* b1    = (const float*)d_in[8];
    const float* Wo    = (const float*)d_in[9];
    const float* bo    = (const float*)d_in[10];
    const float* Wc    = (const float*)d_in[11];
    const float* bc    = (const float*)d_in[12];
    const float* gamma = (const float*)d_in[13];
    const float* beta  = (const float*)d_in[14];
    const float* mu    = (const float*)d_in[15];
    const float* var   = (const float*)d_in[16];
    float* out = (float*)d_out;

    void* p;
    cudaGetSymbolAddress(&p, g_WcatT);  __half* WcatT = (__half*)p;
    cudaGetSymbolAddress(&p, g_W1T);    __half* W1T   = (__half*)p;
    cudaGetSymbolAddress(&p, g_WoT);    __half* WoT   = (__half*)p;
    cudaGetSymbolAddress(&p, g_bcat);   float*  bcat  = (float*)p;
    cudaGetSymbolAddress(&p, g_xh);     __half* xh    = (__half*)p;
    cudaGetSymbolAddress(&p, g_qkvh);   __half* qkvh  = (__half*)p;
    cudaGetSymbolAddress(&p, g_res);    float*  resf  = (float*)p;
    cudaGetSymbolAddress(&p, g_attnh);  __half* attnh = (__half*)p;
    cudaGetSymbolAddress(&p, g_interh); __half* interh = (__half*)p;

    const int SMEM_BR = 65536 + 3 * 16384;      // 114688 (112 KB)
    const int SMEM_ST = NSTAGE * STAGE_BYTES;   // 98304
    cudaFuncSetAttribute(gemm_bres<0, 24>,
                         cudaFuncAttributeMaxDynamicSharedMemorySize, SMEM_BR);
    cudaFuncSetAttribute(gemm_bres<1, 36>,
                         cudaFuncAttributeMaxDynamicSharedMemorySize, SMEM_BR);
    cudaFuncSetAttribute(gemm_out,
                         cudaFuncAttributeMaxDynamicSharedMemorySize, SMEM_ST);

    prep_kernel<<<4608, 256>>>((const float4*)x, (uint2*)xh,
                               Wq, bq, Wk, bk, Wv, bv, W1, Wo, Wc, bc,
                               gamma, beta, mu, var);

    // qkv (fp16, stride 1280) + res (f32) = x @ Wcat + bcat  — persistent
    {
        dim3 grid(CAT / 128, 24);                // 288 CTAs, one wave
        gemm_bres<0, 24><<<grid, 256, SMEM_BR>>>(xh, WcatT, qkvh, resf, QKV, bcat);
    }

    attn_mma_kernel<<<NVOX / 8, 256>>>(qkvh, attnh);

    // inter = relu(attn @ W1 + b1) fp16  — persistent
    {
        dim3 grid(FF / 128, 36);                 // 288 CTAs, one wave
        gemm_bres<1, 36><<<grid, 256, SMEM_BR>>>(attnh, W1T, interh, nullptr, FF, b1);
    }

    // out = (res + inter @ Wo + bo) * bnscale + bnbias
    {
        dim3 grid(VD / 128, NVOX / 128);
        gemm_out<<<grid, 256, SMEM_ST>>>(interh, WoT, out, resf, bo);
    }
}

// round 17
// speedup vs baseline: 1.0645x; 1.0645x over previous
#include <cuda_runtime.h>
#include <cuda_fp16.h>
#include <cstdint>
#include <math.h>

// ---------------------------------------------------------------------------
// Problem constants
// ---------------------------------------------------------------------------
#define NVOX   131072
#define CIN    256
#define NH     16
#define DK     32
#define DV     16
#define VD     256
#define CAT    1536
#define QKV    1280
#define FF     1024

// ---------------------------------------------------------------------------
// Device scratch
// ---------------------------------------------------------------------------
__device__ __half g_WcatT[CAT * CIN];        // [1536,256] K-major fp16
__device__ __half g_W1T[FF * VD];            // [1024,256]
__device__ __half g_WoT[VD * FF];            // [256,1024]
__device__ float  g_bcat[CAT];
__device__ float  g_bnscale[VD];
__device__ float  g_bnbias[VD];
__device__ __half g_xh[(size_t)NVOX * CIN];
__device__ __half g_qkvh[(size_t)NVOX * QKV];
__device__ __half g_resh[(size_t)NVOX * VD]; // residual branch fp16
__device__ __half g_attnh[(size_t)NVOX * VD];
__device__ __half g_interh[(size_t)NVOX * FF];

// ---------------------------------------------------------------------------
// PTX helpers
// ---------------------------------------------------------------------------
__device__ __forceinline__ uint32_t smem_u32(const void* p) {
    uint32_t a;
    asm("{ .reg .u64 t; cvta.to.shared.u64 t, %1; cvt.u32.u64 %0, t; }"
        : "=r"(a) : "l"(p));
    return a;
}
__device__ __forceinline__ void cp16(uint32_t dst, const void* src) {
    asm volatile("cp.async.cg.shared.global [%0], [%1], 16;"
                 :: "r"(dst), "l"(src) : "memory");
}
__device__ __forceinline__ void cp_commit() {
    asm volatile("cp.async.commit_group;" ::: "memory");
}
template<int N>
__device__ __forceinline__ void cp_wait() {
    asm volatile("cp.async.wait_group %0;" :: "n"(N) : "memory");
}
__device__ __forceinline__ uint32_t lds32(uint32_t a) {
    uint32_t v; asm volatile("ld.shared.b32 %0, [%1];" : "=r"(v) : "r"(a)); return v;
}
__device__ __forceinline__ uint32_t lds16(uint32_t a) {
    uint32_t v; asm volatile("ld.shared.u16 %0, [%1];" : "=r"(v) : "r"(a)); return v;
}
#define LDSM4(R, addr) \
    asm volatile("ldmatrix.sync.aligned.m8n8.x4.shared.b16 {%0,%1,%2,%3}, [%4];" \
                 : "=r"((R)[0]), "=r"((R)[1]), "=r"((R)[2]), "=r"((R)[3]) \
                 : "r"(addr))

__device__ __forceinline__ void mma16816(float* d, const uint32_t* a,
                                         uint32_t b0, uint32_t b1) {
    asm volatile(
        "mma.sync.aligned.m16n8k16.row.col.f32.f16.f16.f32 "
        "{%0,%1,%2,%3}, {%4,%5,%6,%7}, {%8,%9}, {%0,%1,%2,%3};"
        : "+f"(d[0]), "+f"(d[1]), "+f"(d[2]), "+f"(d[3])
        : "r"(a[0]), "r"(a[1]), "r"(a[2]), "r"(a[3]), "r"(b0), "r"(b1));
}

// 128B rows, 8 chunks of 16B, conflict-free for ldmatrix & cp.async
__device__ __forceinline__ int swz128(int r, int c) {
    return (r << 7) | (((c ^ r) & 7) << 4);
}
// 512B rows, 32 chunks of 16B; XOR within each 8-chunk (128B) group
__device__ __forceinline__ int swzB512(int r, int c) {
    return (r << 9) | (((c & 24) | ((c ^ r) & 7)) << 4);
}

// ---------------------------------------------------------------------------
// Fused prep: blocks [0,512) pack weights/biases/BN; blocks [512,4608) x->fp16.
// ---------------------------------------------------------------------------
__global__ void prep_kernel(const float4* __restrict__ x4, uint2* __restrict__ xh,
                            const float* __restrict__ Wq, const float* __restrict__ bq,
                            const float* __restrict__ Wk, const float* __restrict__ bk,
                            const float* __restrict__ Wv, const float* __restrict__ bv,
                            const float* __restrict__ W1,
                            const float* __restrict__ Wo,
                            const float* __restrict__ Wc, const float* __restrict__ bc,
                            const float* __restrict__ gamma, const float* __restrict__ beta,
                            const float* __restrict__ mu, const float* __restrict__ var)
{
    if (blockIdx.x < 512) {
        int idx = blockIdx.x * blockDim.x + threadIdx.x;
        const int st = 512 * 256;
        for (int i = idx; i < CAT * CIN; i += st) {
            int n = i >> 8, k = i & 255;
            float w;
            if (n < 512)       w = Wq[k * 512 + n];
            else if (n < 1024) w = Wk[k * 512 + (n - 512)];
            else if (n < 1280) w = Wv[k * 256 + (n - 1024)];
            else               w = Wc[k * 256 + (n - 1280)];
            g_WcatT[i] = __float2half_rn(w);
        }
        for (int i = idx; i < FF * VD; i += st) {
            int n = i >> 8, k = i & 255;
            g_W1T[i] = __float2half_rn(W1[k * FF + n]);
        }
        for (int i = idx; i < VD * FF; i += st) {
            int n = i >> 10, k = i & 1023;
            g_WoT[i] = __float2half_rn(Wo[k * VD + n]);
        }
        for (int i = idx; i < CAT; i += st) {
            float b;
            if (i < 512)       b = bq[i];
            else if (i < 1024) b = bk[i - 512];
            else if (i < 1280) b = bv[i - 1024];
            else               b = bc[i - 1280];
            g_bcat[i] = b;
        }
        for (int i = idx; i < VD; i += st) {
            float s = gamma[i] * rsqrtf(var[i] + 1e-6f);
            g_bnscale[i] = s;
            g_bnbias[i]  = beta[i] - mu[i] * s;
        }
    } else {
        const int n4 = NVOX * CIN / 4;
        int idx = (blockIdx.x - 512) * blockDim.x + threadIdx.x;
        const int st = 4096 * 256;
        for (int i = idx; i < n4; i += st) {
            float4 v = x4[i];
            __half2 h0 = __floats2half2_rn(v.x, v.y);
            __half2 h1 = __floats2half2_rn(v.z, v.w);
            uint2 w;
            w.x = *reinterpret_cast<uint32_t*>(&h0);
            w.y = *reinterpret_cast<uint32_t*>(&h1);
            xh[i] = w;
        }
    }
}

// ---------------------------------------------------------------------------
// B-resident GEMM (K=256): whole B tile (128 x 256 fp16 = 64 KB) loaded to
// smem once; steady loop streams only A (16 KB stages x3). 256 thr, 8 warps
// (2x4), 64x32 warp tiles, 2 CTAs/SM. smem 112 KB/CTA.
//   MODE 0: cols<1280 -> fp16 qkv (stride 1280); cols>=1280 -> relu fp16 res
//   MODE 1: relu -> fp16
// ---------------------------------------------------------------------------
template<int MODE>
__global__ __launch_bounds__(256, 2)
void gemm_bres(const __half* __restrict__ A, const __half* __restrict__ BT,
               void* __restrict__ Cv, __half* __restrict__ resh,
               int Nn, const float* __restrict__ bias)
{
    extern __shared__ char sm[];
    const uint32_t bU = smem_u32(sm);            // B: 64 KB
    const uint32_t aU = bU + 65536;              // A stages: 3 x 16 KB

    const int tid  = threadIdx.x;
    const int wid  = tid >> 5;
    const int lane = tid & 31;
    const int wr = wid >> 2;
    const int wc = wid & 3;
    const int group = lane >> 2;
    const int tig = lane & 3;

    const int row0 = blockIdx.y * 128;
    const int col0 = blockIdx.x * 128;

    float acc[4][4][4];
    #pragma unroll
    for (int mi = 0; mi < 4; mi++)
        #pragma unroll
        for (int ni = 0; ni < 4; ni++)
            #pragma unroll
            for (int r = 0; r < 4; r++) acc[mi][ni][r] = 0.0f;

    // ---- B resident load: 128 rows x 32 chunks(16B) = 4096 cp16, 16/thread
    {
        #pragma unroll
        for (int i = 0; i < 16; i++) {
            int idx = tid + 256 * i;
            int r = idx >> 5, c = idx & 31;
            cp16(bU + swzB512(r, c), &BT[(size_t)(col0 + r) * CIN + c * 8]);
        }
        cp_commit();
    }

    const int ldr = tid >> 3;
    const int ldc = tid & 7;
    auto ldgstsA = [&](int stage, int k0) {
        const uint32_t aS = aU + stage * 16384;
        #pragma unroll
        for (int i = 0; i < 4; i++) {
            int r = ldr + 32 * i;
            cp16(aS + swz128(r, ldc), &A[(size_t)(row0 + r) * CIN + k0 + ldc * 8]);
        }
        cp_commit();
    };

    const int ar = lane & 15, ahi = lane >> 4;
    const int br = (lane & 7) + (lane >> 4) * 8, bhi = (lane >> 3) & 1;

    auto compute = [&](int kt) {
        const uint32_t aS = aU + (kt % 3) * 16384;
        const int cb = kt * 8;                    // B chunk base for this k-tile
        #pragma unroll
        for (int ks = 0; ks < 4; ks++) {
            uint32_t af[4][4], bf[2][4];
            #pragma unroll
            for (int mi = 0; mi < 4; mi++)
                LDSM4(af[mi], aS + swz128(wr * 64 + mi * 16 + ar, ks * 2 + ahi));
            #pragma unroll
            for (int nip = 0; nip < 2; nip++)
                LDSM4(bf[nip], bU + swzB512(wc * 32 + nip * 16 + br,
                                            cb + ks * 2 + bhi));
            #pragma unroll
            for (int mi = 0; mi < 4; mi++)
                #pragma unroll
                for (int ni = 0; ni < 4; ni++) {
                    const int nip = ni >> 1, h = ni & 1;
                    mma16816(acc[mi][ni], af[mi], bf[nip][h * 2], bf[nip][h * 2 + 1]);
                }
        }
    };

    // prologue groups: {B, A0, A1}
    ldgstsA(0, 0);
    ldgstsA(1, 64);

    #pragma unroll
    for (int kt = 0; kt < 4; kt++) {
        if (kt + 1 < 4) cp_wait<1>(); else cp_wait<0>();
        __syncthreads();
        if (kt + 2 < 4) ldgstsA((kt + 2) % 3, (kt + 2) * 64);
        compute(kt);
    }

    // ---- epilogue ----
    __half* Ch = (__half*)Cv;
    #pragma unroll
    for (int mi = 0; mi < 4; mi++) {
        #pragma unroll
        for (int ni = 0; ni < 4; ni++) {
            const int cg = col0 + wc * 32 + ni * 8 + tig * 2;
            const float bi0 = __ldg(&bias[cg]);
            const float bi1 = __ldg(&bias[cg + 1]);
            #pragma unroll
            for (int hf = 0; hf < 2; hf++) {
                const size_t r = (size_t)row0 + wr * 64 + mi * 16 + group + hf * 8;
                float v0 = acc[mi][ni][hf * 2 + 0] + bi0;
                float v1 = acc[mi][ni][hf * 2 + 1] + bi1;
                if (MODE == 0) {
                    if (cg < QKV) {
                        __half2 h = __floats2half2_rn(v0, v1);
                        *reinterpret_cast<uint32_t*>(&Ch[r * QKV + cg]) =
                            *reinterpret_cast<uint32_t*>(&h);
                    } else {
                        __half2 h = __floats2half2_rn(fmaxf(v0, 0.0f), fmaxf(v1, 0.0f));
                        *reinterpret_cast<uint32_t*>(&resh[r * VD + (cg - QKV)]) =
                            *reinterpret_cast<uint32_t*>(&h);
                    }
                } else {
                    __half2 h = __floats2half2_rn(fmaxf(v0, 0.0f), fmaxf(v1, 0.0f));
                    *reinterpret_cast<uint32_t*>(&Ch[r * Nn + cg]) =
                        *reinterpret_cast<uint32_t*>(&h);
                }
            }
        }
    }
}

// ---------------------------------------------------------------------------
// Streaming GEMM (K=1024 final GEMM): out = (res + acc + bias)*bns + bnb
// ---------------------------------------------------------------------------
#define BKT 64
#define STAGE_BYTES 32768
#define NSTAGE 3

__global__ __launch_bounds__(256, 2)
void gemm_out(const __half* __restrict__ A, const __half* __restrict__ BT,
              float* __restrict__ Cf, const __half* __restrict__ resh,
              const float* __restrict__ bias)
{
    extern __shared__ char sm[];
    const uint32_t smemU = smem_u32(sm);

    const int tid  = threadIdx.x;
    const int wid  = tid >> 5;
    const int lane = tid & 31;
    const int wr = wid >> 2;
    const int wc = wid & 3;
    const int group = lane >> 2;
    const int tig = lane & 3;

    const int row0 = blockIdx.y * 128;
    const int col0 = blockIdx.x * 128;
    const int K = FF;
    const int KT = K / BKT;   // 16

    float acc[4][4][4];
    #pragma unroll
    for (int mi = 0; mi < 4; mi++)
        #pragma unroll
        for (int ni = 0; ni < 4; ni++)
            #pragma unroll
            for (int r = 0; r < 4; r++) acc[mi][ni][r] = 0.0f;

    const int ldr = tid >> 3;
    const int ldc = tid & 7;

    auto ldgsts = [&](int stage, int k0) {
        const uint32_t aS = smemU + stage * STAGE_BYTES;
        const uint32_t bS = aS + 16384;
        #pragma unroll
        for (int i = 0; i < 4; i++) {
            int r = ldr + 32 * i;
            cp16(aS + swz128(r, ldc), &A[(size_t)(row0 + r) * K + k0 + ldc * 8]);
            cp16(bS + swz128(r, ldc), &BT[(size_t)(col0 + r) * K + k0 + ldc * 8]);
        }
        cp_commit();
    };

    const int ar = lane & 15, ahi = lane >> 4;
    const int br = (lane & 7) + (lane >> 4) * 8, bhi = (lane >> 3) & 1;

    auto compute = [&](int stage) {
        const uint32_t aS = smemU + stage * STAGE_BYTES;
        const uint32_t bS = aS + 16384;
        #pragma unroll
        for (int ks = 0; ks < 4; ks++) {
            uint32_t af[4][4], bf[2][4];
            #pragma unroll
            for (int mi = 0; mi < 4; mi++)
                LDSM4(af[mi], aS + swz128(wr * 64 + mi * 16 + ar, ks * 2 + ahi));
            #pragma unroll
            for (int nip = 0; nip < 2; nip++)
                LDSM4(bf[nip], bS + swz128(wc * 32 + nip * 16 + br, ks * 2 + bhi));
            #pragma unroll
            for (int mi = 0; mi < 4; mi++)
                #pragma unroll
                for (int ni = 0; ni < 4; ni++) {
                    const int nip = ni >> 1, h = ni & 1;
                    mma16816(acc[mi][ni], af[mi], bf[nip][h * 2], bf[nip][h * 2 + 1]);
                }
        }
    };

    ldgsts(0, 0);
    ldgsts(1, BKT);
    for (int kt = 0; kt < KT; kt++) {
        if (kt + 1 < KT) cp_wait<1>(); else cp_wait<0>();
        __syncthreads();
        if (kt + 2 < KT) ldgsts((kt + 2) % NSTAGE, (kt + 2) * BKT);
        compute(kt % NSTAGE);
    }

    #pragma unroll
    for (int mi = 0; mi < 4; mi++) {
        #pragma unroll
        for (int ni = 0; ni < 4; ni++) {
            const int cg = col0 + wc * 32 + ni * 8 + tig * 2;
            const float bi0 = __ldg(&bias[cg]);
            const float bi1 = __ldg(&bias[cg + 1]);
            const float s0 = g_bnscale[cg], s1 = g_bnscale[cg + 1];
            const float d0 = g_bnbias[cg],  d1 = g_bnbias[cg + 1];
            #pragma unroll
            for (int hf = 0; hf < 2; hf++) {
                const size_t r = (size_t)row0 + wr * 64 + mi * 16 + group + hf * 8;
                uint32_t rw = *reinterpret_cast<const uint32_t*>(&resh[r * VD + cg]);
                __half2 rh = *reinterpret_cast<__half2*>(&rw);
                float2 rr = __half22float2(rh);
                float2 f;
                f.x = (rr.x + acc[mi][ni][hf * 2 + 0] + bi0) * s0 + d0;
                f.y = (rr.y + acc[mi][ni][hf * 2 + 1] + bi1) * s1 + d1;
                *reinterpret_cast<float2*>(&Cf[r * VD + cg]) = f;
            }
        }
    }
}

// ---------------------------------------------------------------------------
// Tensor-core attention: one warp per voxel (unchanged — at DRAM floor)
// ---------------------------------------------------------------------------
#define VOX_B   3328
#define SCALE_S 0.17677669529663687f

__global__ __launch_bounds__(256)
void attn_mma_kernel(const __half* __restrict__ qkvh, __half* __restrict__ outh)
{
    __shared__ __align__(16) char sm[8 * VOX_B];
    const uint32_t smemU = smem_u32(sm);

    const int tid  = threadIdx.x;
    const int wid  = tid >> 5;
    const int lane = tid & 31;
    const size_t vox0 = (size_t)blockIdx.x * 8;

    for (int i = tid; i < 1280; i += 256) {
        int slot = i / 160;
        int j = i - slot * 160;
        int off;
        if (j < 64)       off = (j >> 2) * 80 + (j & 3) * 16;
        else if (j < 128) off = 1280 + ((j - 64) >> 2) * 80 + ((j - 64) & 3) * 16;
        else              off = 2560 + ((j - 128) >> 1) * 48 + ((j - 128) & 1) * 16;
        cp16(smemU + slot * VOX_B + off, qkvh + (vox0 + slot) * QKV + j * 8);
    }
    cp_commit();
    cp_wait<0>();
    __syncthreads();

    const uint32_t qb = smemU + wid * VOX_B;
    const uint32_t kb = qb + 1280;
    const uint32_t vb = qb + 2560;
    const int g4 = lane >> 2;
    const int t4 = lane & 3;

    float sacc[2][4];
    #pragma unroll
    for (int nt = 0; nt < 2; nt++)
        #pragma unroll
        for (int r = 0; r < 4; r++) sacc[nt][r] = 0.0f;

    #pragma unroll
    for (int ks = 0; ks < 2; ks++) {
        uint32_t a[4];
        a[0] = lds32(qb + g4 * 80       + ks * 32 + t4 * 4);
        a[1] = lds32(qb + (g4 + 8) * 80 + ks * 32 + t4 * 4);
        a[2] = lds32(qb + g4 * 80       + ks * 32 + t4 * 4 + 16);
        a[3] = lds32(qb + (g4 + 8) * 80 + ks * 32 + t4 * 4 + 16);
        #pragma unroll
        for (int nt = 0; nt < 2; nt++) {
            uint32_t b0 = lds32(kb + (nt * 8 + g4) * 80 + ks * 32 + t4 * 4);
            uint32_t b1 = lds32(kb + (nt * 8 + g4) * 80 + ks * 32 + t4 * 4 + 16);
            mma16816(sacc[nt], a, b0, b1);
        }
    }

    uint32_t af[4];
    #pragma unroll
    for (int hf = 0; hf < 2; hf++) {
        float v00 = sacc[0][hf * 2]     * SCALE_S;
        float v01 = sacc[0][hf * 2 + 1] * SCALE_S;
        float v10 = sacc[1][hf * 2]     * SCALE_S;
        float v11 = sacc[1][hf * 2 + 1] * SCALE_S;
        float mx = fmaxf(fmaxf(v00, v01), fmaxf(v10, v11));
        mx = fmaxf(mx, __shfl_xor_sync(0xffffffffu, mx, 1));
        mx = fmaxf(mx, __shfl_xor_sync(0xffffffffu, mx, 2));
        float e00 = __expf(v00 - mx), e01 = __expf(v01 - mx);
        float e10 = __expf(v10 - mx), e11 = __expf(v11 - mx);
        float sum = e00 + e01 + e10 + e11;
        sum += __shfl_xor_sync(0xffffffffu, sum, 1);
        sum += __shfl_xor_sync(0xffffffffu, sum, 2);
        float inv = 1.0f / sum;
        __half2 p0 = __floats2half2_rn(e00 * inv, e01 * inv);
        __half2 p1 = __floats2half2_rn(e10 * inv, e11 * inv);
        af[hf]     = *reinterpret_cast<uint32_t*>(&p0);
        af[hf + 2] = *reinterpret_cast<uint32_t*>(&p1);
    }

    float oacc[2][4];
    #pragma unroll
    for (int nt = 0; nt < 2; nt++)
        #pragma unroll
        for (int r = 0; r < 4; r++) oacc[nt][r] = 0.0f;

    #pragma unroll
    for (int nt = 0; nt < 2; nt++) {
        uint32_t b[2];
        #pragma unroll
        for (int reg = 0; reg < 2; reg++) {
            int jr = 2 * t4 + reg * 8;
            uint32_t lo = lds16(vb + jr * 48       + (nt * 8 + g4) * 2);
            uint32_t hi = lds16(vb + (jr + 1) * 48 + (nt * 8 + g4) * 2);
            b[reg] = lo | (hi << 16);
        }
        mma16816(oacc[nt], af, b[0], b[1]);
    }

    __half* dst = outh + (vox0 + wid) * VD;
    #pragma unroll
    for (int nt = 0; nt < 2; nt++) {
        #pragma unroll
        for (int hf = 0; hf < 2; hf++) {
            __half2 h = __floats2half2_rn(oacc[nt][hf * 2], oacc[nt][hf * 2 + 1]);
            int r = g4 + 8 * hf;
            int c = nt * 8 + 2 * t4;
            *reinterpret_cast<uint32_t*>(&dst[r * DV + c]) =
                *reinterpret_cast<uint32_t*>(&h);
        }
    }
}

// ---------------------------------------------------------------------------
// Launch
// ---------------------------------------------------------------------------
extern "C" void kernel_launch(void* const* d_in, const int* in_sizes, int n_in,
                              void* d_out, int out_size)
{
    const float* x     = (const float*)d_in[0];
    const float* Wq    = (const float*)d_in[1];
    const float* bq    = (const float*)d_in[2];
    const float* Wk    = (const float*)d_in[3];
    const float* bk    = (const float*)d_in[4];
    const float* Wv    = (const float*)d_in[5];
    const float* bv    = (const float*)d_in[6];
    const float* W1    = (const float*)d_in[7];
    const float* b1    = (const float*)d_in[8];
    const float* Wo    = (const float*)d_in[9];
    const float* bo    = (const float*)d_in[10];
    const float* Wc    = (const float*)d_in[11];
    const float* bc    = (const float*)d_in[12];
    const float* gamma = (const float*)d_in[13];
    const float* beta  = (const float*)d_in[14];
    const float* mu    = (const float*)d_in[15];
    const float* var   = (const float*)d_in[16];
    float* out = (float*)d_out;

    void* p;
    cudaGetSymbolAddress(&p, g_WcatT);  __half* WcatT = (__half*)p;
    cudaGetSymbolAddress(&p, g_W1T);    __half* W1T   = (__half*)p;
    cudaGetSymbolAddress(&p, g_WoT);    __half* WoT   = (__half*)p;
    cudaGetSymbolAddress(&p, g_bcat);   float*  bcat  = (float*)p;
    cudaGetSymbolAddress(&p, g_xh);     __half* xh    = (__half*)p;
    cudaGetSymbolAddress(&p, g_qkvh);   __half* qkvh  = (__half*)p;
    cudaGetSymbolAddress(&p, g_resh);   __half* resh  = (__half*)p;
    cudaGetSymbolAddress(&p, g_attnh);  __half* attnh = (__half*)p;
    cudaGetSymbolAddress(&p, g_interh); __half* interh = (__half*)p;

    const int SMEM_BR = 65536 + 3 * 16384;      // 114688 (112 KB)
    const int SMEM_ST = NSTAGE * STAGE_BYTES;   // 98304
    cudaFuncSetAttribute(gemm_bres<0>,
                         cudaFuncAttributeMaxDynamicSharedMemorySize, SMEM_BR);
    cudaFuncSetAttribute(gemm_bres<1>,
                         cudaFuncAttributeMaxDynamicSharedMemorySize, SMEM_BR);
    cudaFuncSetAttribute(gemm_out,
                         cudaFuncAttributeMaxDynamicSharedMemorySize, SMEM_ST);

    prep_kernel<<<4608, 256>>>((const float4*)x, (uint2*)xh,
                               Wq, bq, Wk, bk, Wv, bv, W1, Wo, Wc, bc,
                               gamma, beta, mu, var);

    // qkv (fp16, stride 1280) + res (fp16) = x @ Wcat + bcat
    {
        dim3 grid(CAT / 128, NVOX / 128);
        gemm_bres<0><<<grid, 256, SMEM_BR>>>(xh, WcatT, qkvh, resh, QKV, bcat);
    }

    attn_mma_kernel<<<NVOX / 8, 256>>>(qkvh, attnh);

    // inter = relu(attn @ W1 + b1) fp16
    {
        dim3 grid(FF / 128, NVOX / 128);
        gemm_bres<1><<<grid, 256, SMEM_BR>>>(attnh, W1T, interh, nullptr, FF, b1);
    }

    // out = (res + inter @ Wo + bo) * bnscale + bnbias
    {
        dim3 grid(VD / 128, NVOX / 128);
        gemm_out<<<grid, 256, SMEM_ST>>>(interh, WoT, out, resh, bo);
    }
}